// round 7
// baseline (speedup 1.0000x reference)
#include <cuda_runtime.h>
#include <math.h>
#include <stdint.h>

#define NE    2048
#define FEAT  512
#define REST  8
#define HEAD  8
#define HL    512
#define NCOL  16384
#define OUTC  (HEAD*512)
#define BK    16
#define PADK  20
#define PADN  136
#define STG   3
#define ASTR  (128*PADK)
#define SMEM_BYTES (2 * STG * ASTR * 4)   // 61440

// ---------------- scratch ----------------------------------------------------
__device__ float g_Y  [(size_t)3 * HEAD * NE * 512];
__device__ float g_xt [(size_t)NCOL * FEAT];
__device__ float g_W  [(size_t)3 * HL * FEAT];
__device__ float g_S  [(size_t)HEAD * NE * NE];
__device__ float g_ss [3 * NE];
__device__ float g_rs [(size_t)HEAD * NE];

// ---------------- helpers ----------------------------------------------------
__device__ __forceinline__ uint32_t smem_u32(const void* p) {
    uint32_t a;
    asm("{ .reg .u64 t; cvta.to.shared.u64 t, %1; cvt.u32.u64 %0, t; }" : "=r"(a) : "l"(p));
    return a;
}
__device__ __forceinline__ float f2tf(float f) {
    uint32_t u;
    asm("cvt.rna.tf32.f32 %0, %1;" : "=r"(u) : "f"(f));
    return __uint_as_float(u);
}
__device__ __forceinline__ void mma8(float* c, const uint32_t* a, const uint32_t* b) {
    asm volatile(
        "mma.sync.aligned.m16n8k8.row.col.f32.tf32.tf32.f32 "
        "{%0,%1,%2,%3}, {%4,%5,%6,%7}, {%8,%9}, {%0,%1,%2,%3};"
        : "+f"(c[0]), "+f"(c[1]), "+f"(c[2]), "+f"(c[3])
        : "r"(a[0]), "r"(a[1]), "r"(a[2]), "r"(a[3]), "r"(b[0]), "r"(b[1]));
}
__device__ __forceinline__ void cp16(uint32_t dst, const float* src) {
    uint64_t g;
    asm("cvta.to.global.u64 %0, %1;" : "=l"(g) : "l"(src));
    asm volatile("cp.async.cg.shared.global [%0], [%1], 16;" :: "r"(dst), "l"(g));
}
__device__ __forceinline__ uint32_t fb(float f) { return __float_as_uint(f); }

// 128 rows x 16 K-major tile (256 threads: 2 chunks each)
__device__ __forceinline__ void ld_k(float* S, const float* gp, int ldk, int k0, int tid) {
#pragma unroll
    for (int i = 0; i < 2; i++) {
        int idx = tid + i * 256;
        int row = idx >> 2, ch = idx & 3;
        cp16(smem_u32(S + row * PADK + ch * 4), gp + (size_t)row * ldk + k0 + ch * 4);
    }
}
// 16 k-rows x 128 n-cols MN-major tile
__device__ __forceinline__ void ld_mn(float* S, const float* gp, int ldn, int k0, int tid) {
#pragma unroll
    for (int i = 0; i < 2; i++) {
        int idx = tid + i * 256;
        int kk = idx >> 5, ch = idx & 31;
        cp16(smem_u32(S + kk * PADN + ch * 4), gp + (size_t)(k0 + kk) * ldn + ch * 4);
    }
}

struct Acc { float a[2][8][4]; };       // 32x64 warp tile
struct Frag { uint32_t af[2][4]; uint32_t bf[8][2]; };

template<int BMN>
__device__ __forceinline__ void ldfrag(Frag& f, const float* As, const float* Bs,
                                       int k0, int wm, int wn, int g8, int tg) {
#pragma unroll
    for (int mt = 0; mt < 2; mt++) {
        int r0 = wm + mt * 16 + g8;
        f.af[mt][0] = fb(As[r0 * PADK + k0 + tg]);
        f.af[mt][1] = fb(As[(r0 + 8) * PADK + k0 + tg]);
        f.af[mt][2] = fb(As[r0 * PADK + k0 + tg + 4]);
        f.af[mt][3] = fb(As[(r0 + 8) * PADK + k0 + tg + 4]);
    }
#pragma unroll
    for (int nt = 0; nt < 8; nt++) {
        int rn = wn + nt * 8 + g8;
        if (BMN) {
            f.bf[nt][0] = fb(Bs[(k0 + tg) * PADN + rn]);
            f.bf[nt][1] = fb(Bs[(k0 + tg + 4) * PADN + rn]);
        } else {
            f.bf[nt][0] = fb(Bs[rn * PADK + k0 + tg]);
            f.bf[nt][1] = fb(Bs[rn * PADK + k0 + tg + 4]);
        }
    }
}
__device__ __forceinline__ void mma_all(Acc& F, const Frag& f) {
#pragma unroll
    for (int mt = 0; mt < 2; mt++)
#pragma unroll
        for (int nt = 0; nt < 8; nt++)
            mma8(F.a[mt][nt], f.af[mt], f.bf[nt]);
}

// ---------------- 3-stage pipelined mainloop + register double-buffer --------
template<int BMN>
__device__ __forceinline__ void gemm_main(Acc& F, const float* A, const float* B,
                                          int K, int ldb, float* sA, float* sB) {
    const int tid = threadIdx.x;
    const int lane = tid & 31, wid = tid >> 5;
    const int g8 = lane >> 2, tg = lane & 3;
    const int wm = (wid & 3) * 32, wn = (wid >> 2) * 64;
    const int BSTR = BMN ? BK * PADN : 128 * PADK;

#pragma unroll
    for (int mt = 0; mt < 2; mt++)
#pragma unroll
        for (int nt = 0; nt < 8; nt++)
#pragma unroll
            for (int j = 0; j < 4; j++) F.a[mt][nt][j] = 0.f;

#pragma unroll
    for (int s = 0; s < STG - 1; s++) {
        ld_k(sA + s * ASTR, A, K, s * BK, tid);
        if (BMN) ld_mn(sB + s * BSTR, B, ldb, s * BK, tid);
        else     ld_k(sB + s * BSTR, B, K, s * BK, tid);
        asm volatile("cp.async.commit_group;" ::: "memory");
    }

    const int KT = K / BK;
    int ls = STG - 1;
    for (int kt = 0; kt < KT; kt++) {
        asm volatile("cp.async.wait_group %0;" :: "n"(STG - 2) : "memory");
        __syncthreads();
        if (kt + STG - 1 < KT) {
            ld_k(sA + ls * ASTR, A, K, (kt + STG - 1) * BK, tid);
            if (BMN) ld_mn(sB + ls * BSTR, B, ldb, (kt + STG - 1) * BK, tid);
            else     ld_k(sB + ls * BSTR, B, K, (kt + STG - 1) * BK, tid);
            ls = (ls + 1 == STG) ? 0 : ls + 1;
        }
        asm volatile("cp.async.commit_group;" ::: "memory");

        int buf = kt % STG;
        const float* As = sA + buf * ASTR;
        const float* Bs = sB + buf * BSTR;

        Frag f0, f1;
        ldfrag<BMN>(f0, As, Bs, 0, wm, wn, g8, tg);
        ldfrag<BMN>(f1, As, Bs, 8, wm, wn, g8, tg);
        mma_all(F, f0);
        mma_all(F, f1);
    }
    __syncthreads();
}

// ---------------- init / prep / transpose ------------------------------------
__global__ __launch_bounds__(256) void init_zero() {
    int i = blockIdx.x * 256 + threadIdx.x;
    if (i < 3 * NE) g_ss[i] = 0.f;
    if (i < HEAD * NE) g_rs[i] = 0.f;
}
__global__ __launch_bounds__(256) void prep_w(const float* __restrict__ Wq,
                                              const float* __restrict__ Wk,
                                              const float* __restrict__ Wd) {
    int idx = (blockIdx.x * 256 + threadIdx.x) * 4;
    int p = idx >> 18, off = idx & 262143;
    const float* W = (p == 0) ? Wq : (p == 1) ? Wk : Wd;
    float4 t = *(const float4*)(W + off);
    t.x = f2tf(t.x); t.y = f2tf(t.y); t.z = f2tf(t.z); t.w = f2tf(t.w);
    *(float4*)(g_W + idx) = t;
}
__global__ __launch_bounds__(256) void transpose_x(const float* __restrict__ x) {
    __shared__ float s[512 * 9];
    const int n = blockIdx.x, tid = threadIdx.x;
    const float* src = x + (size_t)n * 4096;
#pragma unroll
    for (int i = 0; i < 4; i++) {
        int v = (tid + i * 256) * 4;
        float4 t = *(const float4*)(src + v);
        int f = v >> 3, rr = v & 7;
        s[f * 9 + rr + 0] = t.x; s[f * 9 + rr + 1] = t.y;
        s[f * 9 + rr + 2] = t.z; s[f * 9 + rr + 3] = t.w;
    }
    __syncthreads();
#pragma unroll
    for (int rr = 0; rr < 8; rr++)
#pragma unroll
        for (int q = 0; q < 2; q++) {
            int f = tid + q * 256;
            g_xt[((size_t)n * 8 + rr) * 512 + f] = f2tf(s[f * 9 + rr]);
        }
}

// ---------------- projection GEMM + fused sum-of-squares --------------------
__global__ __launch_bounds__(256) void proj_tc() {
    extern __shared__ float dsm[];
    __shared__ float csum[128];
    float* sA = dsm;
    float* sB = dsm + STG * ASTR;
    const int p = blockIdx.z;
    const int m0 = blockIdx.y * 128, c0 = blockIdx.x * 128;

    const int tid = threadIdx.x, lane = tid & 31, wid = tid >> 5;
    const int g8 = lane >> 2, tg = lane & 3;
    const int wm = (wid & 3) * 32, wn = (wid >> 2) * 64;

    if (tid < 128) csum[tid] = 0.f;

    Acc F;
    gemm_main<0>(F, g_W + (size_t)p * HL * FEAT + (size_t)m0 * FEAT,
                 g_xt + (size_t)c0 * FEAT, FEAT, 0, sA, sB);

    float* base = g_Y + (size_t)p * HEAD * NE * 512;
    float sq[8];
#pragma unroll
    for (int nt = 0; nt < 8; nt++) sq[nt] = 0.f;

#pragma unroll
    for (int mt = 0; mt < 2; mt++)
#pragma unroll
        for (int half = 0; half < 2; half++) {
            int row = m0 + wm + mt * 16 + g8 + half * 8;
            int hh = row >> 6, l = row & 63;
#pragma unroll
            for (int nt = 0; nt < 8; nt++) {
                int col = c0 + wn + nt * 8 + 2 * tg;
                int n = col >> 3, r = col & 7;
                float v0 = f2tf(F.a[mt][nt][half * 2 + 0]);
                float v1 = f2tf(F.a[mt][nt][half * 2 + 1]);
                *(float2*)(base + ((size_t)hh * NE + n) * 512 + l * 8 + r) = make_float2(v0, v1);
                sq[nt] += v0 * v0 + v1 * v1;
            }
        }
#pragma unroll
    for (int nt = 0; nt < 8; nt++) {
        float v = sq[nt];
        v += __shfl_down_sync(0xffffffffu, v, 4);
        v += __shfl_down_sync(0xffffffffu, v, 8);
        v += __shfl_down_sync(0xffffffffu, v, 16);
        if (g8 == 0) atomicAdd(&csum[wn + nt * 8 + 2 * tg], v);
    }
    __syncthreads();
    if (tid < 16) {
        float s = 0.f;
#pragma unroll
        for (int j = 0; j < 8; j += 2) s += csum[tid * 8 + j];
        atomicAdd(&g_ss[p * NE + (c0 >> 3) + tid], s);
    }
}

// ---------------- scores GEMM + fused exp/softmax-numerator -----------------
__global__ __launch_bounds__(256) void scores_tc() {
    extern __shared__ float dsm[];
    __shared__ float rsum[128];
    float* sA = dsm;
    float* sB = dsm + STG * ASTR;
    const int h = blockIdx.z;
    const int m0 = blockIdx.y * 128, n0 = blockIdx.x * 128;

    const int tid = threadIdx.x, lane = tid & 31, wid = tid >> 5;
    const int g8 = lane >> 2, tg = lane & 3;
    const int wm = (wid & 3) * 32, wn = (wid >> 2) * 64;

    if (tid < 128) rsum[tid] = 0.f;

    Acc F;
    gemm_main<0>(F, g_Y + ((size_t)h * NE + m0) * 512,
                 g_Y + (((size_t)HEAD + h) * NE + n0) * 512, 512, 0, sA, sB);

    float rk[8][2], rd[8][2];
#pragma unroll
    for (int nt = 0; nt < 8; nt++) {
        int col = n0 + wn + nt * 8 + 2 * tg;
        rk[nt][0] = rsqrtf(g_ss[NE + col]);     rk[nt][1] = rsqrtf(g_ss[NE + col + 1]);
        rd[nt][0] = rsqrtf(g_ss[2 * NE + col]); rd[nt][1] = rsqrtf(g_ss[2 * NE + col + 1]);
    }

#pragma unroll
    for (int mt = 0; mt < 2; mt++)
#pragma unroll
        for (int half = 0; half < 2; half++) {
            int row = m0 + wm + mt * 16 + g8 + half * 8;
            float rq = rsqrtf(g_ss[row]);
            float rs = 0.f;
#pragma unroll
            for (int nt = 0; nt < 8; nt++) {
                int col = n0 + wn + nt * 8 + 2 * tg;
                float e0 = __expf(F.a[mt][nt][half * 2 + 0] * rq * rk[nt][0]);
                float e1 = __expf(F.a[mt][nt][half * 2 + 1] * rq * rk[nt][1]);
                rs += e0 + e1;
                float p0 = f2tf(e0 * rd[nt][0]);
                float p1 = f2tf(e1 * rd[nt][1]);
                *(float2*)(g_S + ((size_t)h * NE + row) * NE + col) = make_float2(p0, p1);
            }
            rs += __shfl_down_sync(0xffffffffu, rs, 1);
            rs += __shfl_down_sync(0xffffffffu, rs, 2);
            if (tg == 0) atomicAdd(&rsum[wm + mt * 16 + g8 + half * 8], rs);
        }
    __syncthreads();
    if (tid < 128) atomicAdd(&g_rs[(size_t)h * NE + m0 + tid], rsum[tid]);
}

// ---------------- combine GEMM (B MN-major), scale rows by 1/rowsum ---------
__global__ __launch_bounds__(256) void combine_tc(float* __restrict__ out) {
    extern __shared__ float dsm[];
    float* sA = dsm;
    float* sB = dsm + STG * ASTR;
    const int h = blockIdx.z;
    const int m0 = blockIdx.y * 128, lr0 = blockIdx.x * 128;

    Acc F;
    gemm_main<1>(F, g_S + ((size_t)h * NE + m0) * NE,
                 g_Y + ((size_t)2 * HEAD + h) * NE * 512 + lr0, NE, 512, sA, sB);

    const int tid = threadIdx.x, lane = tid & 31, wid = tid >> 5;
    const int g8 = lane >> 2, tg = lane & 3;
    const int wm = (wid & 3) * 32, wn = (wid >> 2) * 64;

#pragma unroll
    for (int mt = 0; mt < 2; mt++)
#pragma unroll
        for (int half = 0; half < 2; half++) {
            int row = m0 + wm + mt * 16 + g8 + half * 8;
            float inv = 1.0f / g_rs[(size_t)h * NE + row];
#pragma unroll
            for (int nt = 0; nt < 8; nt++) {
                int col = lr0 + wn + nt * 8 + 2 * tg;
                float v0 = F.a[mt][nt][half * 2 + 0] * inv;
                float v1 = F.a[mt][nt][half * 2 + 1] * inv;
                *(float2*)(out + (size_t)row * OUTC + h * 512 + col) = make_float2(v0, v1);
            }
        }
}

// ---------------------------------------------------------------------------
extern "C" void kernel_launch(void* const* d_in, const int* in_sizes, int n_in,
                              void* d_out, int out_size) {
    const float* x  = (const float*)d_in[0];
    const float* Wq = (const float*)d_in[1];
    const float* Wk = (const float*)d_in[2];
    const float* Wd = (const float*)d_in[3];
    float* out = (float*)d_out;

    cudaFuncSetAttribute(proj_tc,    cudaFuncAttributeMaxDynamicSharedMemorySize, SMEM_BYTES);
    cudaFuncSetAttribute(scores_tc,  cudaFuncAttributeMaxDynamicSharedMemorySize, SMEM_BYTES);
    cudaFuncSetAttribute(combine_tc, cudaFuncAttributeMaxDynamicSharedMemorySize, SMEM_BYTES);

    init_zero<<<64, 256>>>();
    prep_w<<<768, 256>>>(Wq, Wk, Wd);
    transpose_x<<<NE, 256>>>(x);
    proj_tc<<<dim3(NCOL / 128, HL / 128, 3), 256, SMEM_BYTES>>>();
    scores_tc<<<dim3(NE / 128, NE / 128, HEAD), 256, SMEM_BYTES>>>();
    combine_tc<<<dim3(512 / 128, NE / 128, HEAD), 256, SMEM_BYTES>>>(out);
}

// round 8
// speedup vs baseline: 1.8217x; 1.8217x over previous
#include <cuda_runtime.h>
#include <cuda_fp16.h>
#include <math.h>
#include <stdint.h>

#define NE    2048
#define FEAT  512
#define REST  8
#define HEAD  8
#define HL    512
#define NCOL  16384
#define OUTC  (HEAD*512)
#define BKH   32                  // K per smem tile, in halves
#define PADH  40                  // halves per row (20 half2 words; conflict-free)
#define ASTRH (128*PADH)
#define STG   3
#define SMEM_BYTES (2 * STG * ASTRH * 2)   // 61440 bytes

// ---------------- scratch ----------------------------------------------------
__device__ __half g_Y  [(size_t)2 * HEAD * NE * 512];  // q,k: [p][h][n][lr]
__device__ __half g_Yd [(size_t)HEAD * 512 * NE];      // d:   [h][lr][m] (K-major for combine)
__device__ __half g_xt [(size_t)NCOL * FEAT];          // xt[(n*8+r)][f]
__device__ __half g_W  [(size_t)3 * HL * FEAT];
__device__ __half g_S  [(size_t)HEAD * NE * NE];       // exp(scores)*rd
__device__ float  g_ss [3 * NE];
__device__ float  g_rs [(size_t)HEAD * NE];

// ---------------- helpers ----------------------------------------------------
__device__ __forceinline__ uint32_t smem_u32(const void* p) {
    uint32_t a;
    asm("{ .reg .u64 t; cvta.to.shared.u64 t, %1; cvt.u32.u64 %0, t; }" : "=r"(a) : "l"(p));
    return a;
}
__device__ __forceinline__ void mma16(float* c, const uint32_t* a, const uint32_t* b) {
    asm volatile(
        "mma.sync.aligned.m16n8k16.row.col.f32.f16.f16.f32 "
        "{%0,%1,%2,%3}, {%4,%5,%6,%7}, {%8,%9}, {%0,%1,%2,%3};"
        : "+f"(c[0]), "+f"(c[1]), "+f"(c[2]), "+f"(c[3])
        : "r"(a[0]), "r"(a[1]), "r"(a[2]), "r"(a[3]), "r"(b[0]), "r"(b[1]));
}
__device__ __forceinline__ void cp16(uint32_t dst, const void* src) {
    uint64_t g;
    asm("cvta.to.global.u64 %0, %1;" : "=l"(g) : "l"(src));
    asm volatile("cp.async.cg.shared.global [%0], [%1], 16;" :: "r"(dst), "l"(g));
}

// 128 rows x 32 halves K-major tile (128 threads: 4 chunks each)
__device__ __forceinline__ void ld_k(__half* S, const __half* gp, int ldk, int k0, int tid) {
#pragma unroll
    for (int i = 0; i < 4; i++) {
        int idx = tid + i * 128;          // 0..511
        int row = idx >> 2, ch = idx & 3;
        cp16(smem_u32(S + row * PADH + ch * 8), gp + (size_t)row * ldk + k0 + ch * 8);
    }
}

struct Acc { float a[4][8][4]; };

// ---------------- 3-stage pipelined fp16 NT mainloop -------------------------
__device__ __forceinline__ void gemm_main(Acc& F, const __half* A, const __half* B,
                                          int K, __half* sA, __half* sB) {
    const int tid = threadIdx.x;
    const int lane = tid & 31, wid = tid >> 5;
    const int g8 = lane >> 2, tg = lane & 3;
    const int wm = (wid & 1) * 64, wn = (wid >> 1) * 64;

#pragma unroll
    for (int mt = 0; mt < 4; mt++)
#pragma unroll
        for (int nt = 0; nt < 8; nt++)
#pragma unroll
            for (int j = 0; j < 4; j++) F.a[mt][nt][j] = 0.f;

#pragma unroll
    for (int s = 0; s < STG - 1; s++) {
        ld_k(sA + s * ASTRH, A, K, s * BKH, tid);
        ld_k(sB + s * ASTRH, B, K, s * BKH, tid);
        asm volatile("cp.async.commit_group;" ::: "memory");
    }

    const int KT = K / BKH;
    int ls = STG - 1;
    for (int kt = 0; kt < KT; kt++) {
        asm volatile("cp.async.wait_group %0;" :: "n"(STG - 2) : "memory");
        __syncthreads();
        if (kt + STG - 1 < KT) {
            ld_k(sA + ls * ASTRH, A, K, (kt + STG - 1) * BKH, tid);
            ld_k(sB + ls * ASTRH, B, K, (kt + STG - 1) * BKH, tid);
            ls = (ls + 1 == STG) ? 0 : ls + 1;
        }
        asm volatile("cp.async.commit_group;" ::: "memory");

        int buf = kt % STG;
        const uint32_t* A2 = (const uint32_t*)(sA + buf * ASTRH);
        const uint32_t* B2 = (const uint32_t*)(sB + buf * ASTRH);
#pragma unroll
        for (int ks = 0; ks < 2; ks++) {
            const int kw = ks * 8;        // half2-word offset
            uint32_t af[4][4], bf[8][2];
#pragma unroll
            for (int mt = 0; mt < 4; mt++) {
                int r0 = wm + mt * 16 + g8;
                af[mt][0] = A2[r0 * 20 + kw + tg];
                af[mt][1] = A2[(r0 + 8) * 20 + kw + tg];
                af[mt][2] = A2[r0 * 20 + kw + tg + 4];
                af[mt][3] = A2[(r0 + 8) * 20 + kw + tg + 4];
            }
#pragma unroll
            for (int nt = 0; nt < 8; nt++) {
                int rn = wn + nt * 8 + g8;
                bf[nt][0] = B2[rn * 20 + kw + tg];
                bf[nt][1] = B2[rn * 20 + kw + tg + 4];
            }
#pragma unroll
            for (int mt = 0; mt < 4; mt++)
#pragma unroll
                for (int nt = 0; nt < 8; nt++)
                    mma16(F.a[mt][nt], af[mt], bf[nt]);
        }
    }
    __syncthreads();
}

// ---------------- init / prep / transpose ------------------------------------
__global__ __launch_bounds__(256) void init_zero() {
    int i = blockIdx.x * 256 + threadIdx.x;
    if (i < 3 * NE) g_ss[i] = 0.f;
    if (i < HEAD * NE) g_rs[i] = 0.f;
}
__global__ __launch_bounds__(256) void prep_w(const float* __restrict__ Wq,
                                              const float* __restrict__ Wk,
                                              const float* __restrict__ Wd) {
    int idx = (blockIdx.x * 256 + threadIdx.x) * 4;
    int p = idx >> 18, off = idx & 262143;
    const float* W = (p == 0) ? Wq : (p == 1) ? Wk : Wd;
    float4 t = *(const float4*)(W + off);
    __half2 h0 = make_half2(__float2half_rn(t.x), __float2half_rn(t.y));
    __half2 h1 = make_half2(__float2half_rn(t.z), __float2half_rn(t.w));
    *(__half2*)(g_W + idx) = h0;
    *(__half2*)(g_W + idx + 2) = h1;
}
__global__ __launch_bounds__(256) void transpose_x(const float* __restrict__ x) {
    __shared__ float s[512 * 9];
    const int n = blockIdx.x, tid = threadIdx.x;
    const float* src = x + (size_t)n * 4096;
#pragma unroll
    for (int i = 0; i < 4; i++) {
        int v = (tid + i * 256) * 4;
        float4 t = *(const float4*)(src + v);
        int f = v >> 3, rr = v & 7;
        s[f * 9 + rr + 0] = t.x; s[f * 9 + rr + 1] = t.y;
        s[f * 9 + rr + 2] = t.z; s[f * 9 + rr + 3] = t.w;
    }
    __syncthreads();
#pragma unroll
    for (int rr = 0; rr < 8; rr++) {
        int f = tid * 2;
        __half2 h = make_half2(__float2half_rn(s[f * 9 + rr]),
                               __float2half_rn(s[(f + 1) * 9 + rr]));
        *(__half2*)(g_xt + ((size_t)n * 8 + rr) * 512 + f) = h;
    }
}

// ---------------- projection GEMM + fused sum-of-squares --------------------
__global__ __launch_bounds__(128) void proj_tc() {
    extern __shared__ __half dsm[];
    __shared__ float csum[128];
    __half* sA = dsm;
    __half* sB = dsm + STG * ASTRH;
    const int p = blockIdx.z;
    const int m0 = blockIdx.y * 128, c0 = blockIdx.x * 128;

    const int tid = threadIdx.x, lane = tid & 31, wid = tid >> 5;
    const int g8 = lane >> 2, tg = lane & 3;
    const int wm = (wid & 1) * 64, wn = (wid >> 1) * 64;

    if (tid < 128) csum[tid] = 0.f;

    Acc F;
    gemm_main(F, g_W + (size_t)p * HL * FEAT + (size_t)m0 * FEAT,
              g_xt + (size_t)c0 * FEAT, FEAT, sA, sB);

    float sq[8];
#pragma unroll
    for (int nt = 0; nt < 8; nt++) sq[nt] = 0.f;

    if (p < 2) {
        __half* base = g_Y + (size_t)p * HEAD * NE * 512;
#pragma unroll
        for (int mt = 0; mt < 4; mt++)
#pragma unroll
            for (int half = 0; half < 2; half++) {
                int row = m0 + wm + mt * 16 + g8 + half * 8;
                int hh = row >> 6, l = row & 63;
#pragma unroll
                for (int nt = 0; nt < 8; nt++) {
                    int col = c0 + wn + nt * 8 + 2 * tg;
                    int n = col >> 3, r = col & 7;
                    __half h0 = __float2half_rn(F.a[mt][nt][half * 2 + 0]);
                    __half h1 = __float2half_rn(F.a[mt][nt][half * 2 + 1]);
                    float v0 = __half2float(h0), v1 = __half2float(h1);
                    *(__half2*)(base + ((size_t)hh * NE + n) * 512 + l * 8 + r) = make_half2(h0, h1);
                    sq[nt] += v0 * v0 + v1 * v1;
                }
            }
    } else {
        // d: [h][lr][m], 16B packed stores of 8 consecutive m
        int mb = (c0 >> 3) + (wn >> 3);
#pragma unroll
        for (int mt = 0; mt < 4; mt++)
#pragma unroll
            for (int half = 0; half < 2; half++) {
                int row = m0 + wm + mt * 16 + g8 + half * 8;
                int hh = row >> 6, l = row & 63;
#pragma unroll
                for (int par = 0; par < 2; par++) {
                    __half hv[8];
#pragma unroll
                    for (int nt = 0; nt < 8; nt++) {
                        hv[nt] = __float2half_rn(F.a[mt][nt][half * 2 + par]);
                        float v = __half2float(hv[nt]);
                        sq[nt] += v * v;
                    }
                    int lr = l * 8 + 2 * tg + par;
                    *(uint4*)(g_Yd + ((size_t)hh * 512 + lr) * NE + mb) = *(uint4*)hv;
                }
            }
    }
#pragma unroll
    for (int nt = 0; nt < 8; nt++) {
        float v = sq[nt];
        v += __shfl_down_sync(0xffffffffu, v, 4);
        v += __shfl_down_sync(0xffffffffu, v, 8);
        v += __shfl_down_sync(0xffffffffu, v, 16);
        if (g8 == 0) atomicAdd(&csum[wn + nt * 8 + 2 * tg], v);
    }
    __syncthreads();
    if (tid < 16) {
        float s = 0.f;
#pragma unroll
        for (int j = 0; j < 8; j += 2) s += csum[tid * 8 + j];
        atomicAdd(&g_ss[p * NE + (c0 >> 3) + tid], s);
    }
}

// ---------------- scores GEMM + fused exp/softmax-numerator -----------------
__global__ __launch_bounds__(128) void scores_tc() {
    extern __shared__ __half dsm[];
    __shared__ float rsum[128];
    __half* sA = dsm;
    __half* sB = dsm + STG * ASTRH;
    const int h = blockIdx.z;
    const int m0 = blockIdx.y * 128, n0 = blockIdx.x * 128;

    const int tid = threadIdx.x, lane = tid & 31, wid = tid >> 5;
    const int g8 = lane >> 2, tg = lane & 3;
    const int wm = (wid & 1) * 64, wn = (wid >> 1) * 64;

    if (tid < 128) rsum[tid] = 0.f;

    Acc F;
    gemm_main(F, g_Y + ((size_t)h * NE + m0) * 512,
              g_Y + (((size_t)HEAD + h) * NE + n0) * 512, 512, sA, sB);

    float rk[8][2], rd[8][2];
#pragma unroll
    for (int nt = 0; nt < 8; nt++) {
        int col = n0 + wn + nt * 8 + 2 * tg;
        rk[nt][0] = rsqrtf(g_ss[NE + col]);     rk[nt][1] = rsqrtf(g_ss[NE + col + 1]);
        rd[nt][0] = rsqrtf(g_ss[2 * NE + col]); rd[nt][1] = rsqrtf(g_ss[2 * NE + col + 1]);
    }

#pragma unroll
    for (int mt = 0; mt < 4; mt++)
#pragma unroll
        for (int half = 0; half < 2; half++) {
            int row = m0 + wm + mt * 16 + g8 + half * 8;
            float rq = rsqrtf(g_ss[row]);
            float rs = 0.f;
#pragma unroll
            for (int nt = 0; nt < 8; nt++) {
                int col = n0 + wn + nt * 8 + 2 * tg;
                float e0 = __expf(F.a[mt][nt][half * 2 + 0] * rq * rk[nt][0]);
                float e1 = __expf(F.a[mt][nt][half * 2 + 1] * rq * rk[nt][1]);
                rs += e0 + e1;
                __half2 ph = make_half2(__float2half_rn(e0 * rd[nt][0]),
                                        __float2half_rn(e1 * rd[nt][1]));
                *(__half2*)(g_S + ((size_t)h * NE + row) * NE + col) = ph;
            }
            rs += __shfl_down_sync(0xffffffffu, rs, 1);
            rs += __shfl_down_sync(0xffffffffu, rs, 2);
            if (tg == 0) atomicAdd(&rsum[wm + mt * 16 + g8 + half * 8], rs);
        }
    __syncthreads();
    if (tid < 128) atomicAdd(&g_rs[(size_t)h * NE + m0 + tid], rsum[tid]);
}

// ---------------- combine GEMM (all K-major), scale rows by 1/rowsum --------
__global__ __launch_bounds__(128) void combine_tc(float* __restrict__ out) {
    extern __shared__ __half dsm[];
    __half* sA = dsm;
    __half* sB = dsm + STG * ASTRH;
    const int h = blockIdx.z;
    const int m0 = blockIdx.y * 128, lr0 = blockIdx.x * 128;

    Acc F;
    gemm_main(F, g_S + ((size_t)h * NE + m0) * NE,
              g_Yd + ((size_t)h * 512 + lr0) * NE, NE, sA, sB);

    const int tid = threadIdx.x, lane = tid & 31, wid = tid >> 5;
    const int g8 = lane >> 2, tg = lane & 3;
    const int wm = (wid & 1) * 64, wn = (wid >> 1) * 64;

#pragma unroll
    for (int mt = 0; mt < 4; mt++)
#pragma unroll
        for (int half = 0; half < 2; half++) {
            int row = m0 + wm + mt * 16 + g8 + half * 8;
            float inv = 1.0f / g_rs[(size_t)h * NE + row];
#pragma unroll
            for (int nt = 0; nt < 8; nt++) {
                int col = lr0 + wn + nt * 8 + 2 * tg;
                float v0 = F.a[mt][nt][half * 2 + 0] * inv;
                float v1 = F.a[mt][nt][half * 2 + 1] * inv;
                *(float2*)(out + (size_t)row * OUTC + h * 512 + col) = make_float2(v0, v1);
            }
        }
}

// ---------------------------------------------------------------------------
extern "C" void kernel_launch(void* const* d_in, const int* in_sizes, int n_in,
                              void* d_out, int out_size) {
    const float* x  = (const float*)d_in[0];
    const float* Wq = (const float*)d_in[1];
    const float* Wk = (const float*)d_in[2];
    const float* Wd = (const float*)d_in[3];
    float* out = (float*)d_out;

    cudaFuncSetAttribute(proj_tc,    cudaFuncAttributeMaxDynamicSharedMemorySize, SMEM_BYTES);
    cudaFuncSetAttribute(scores_tc,  cudaFuncAttributeMaxDynamicSharedMemorySize, SMEM_BYTES);
    cudaFuncSetAttribute(combine_tc, cudaFuncAttributeMaxDynamicSharedMemorySize, SMEM_BYTES);

    init_zero<<<64, 256>>>();
    prep_w<<<768, 256>>>(Wq, Wk, Wd);
    transpose_x<<<NE, 256>>>(x);
    proj_tc<<<dim3(NCOL / 128, HL / 128, 3), 128, SMEM_BYTES>>>();
    scores_tc<<<dim3(NE / 128, NE / 128, HEAD), 128, SMEM_BYTES>>>();
    combine_tc<<<dim3(512 / 128, NE / 128, HEAD), 128, SMEM_BYTES>>>(out);
}

// round 9
// speedup vs baseline: 1.9615x; 1.0768x over previous
#include <cuda_runtime.h>
#include <cuda_fp16.h>
#include <math.h>
#include <stdint.h>

#define NE    2048
#define FEAT  512
#define REST  8
#define HEAD  8
#define HL    512
#define NCOL  16384
#define OUTC  (HEAD*512)
#define BKH   32                  // K per smem tile, in halves
#define PADH  40                  // halves per row; ldmatrix conflict-free
#define ASTRH (128*PADH)
#define STG   4
#define SMEM_BYTES (2 * STG * ASTRH * 2)   // 81920 bytes

// ---------------- scratch ----------------------------------------------------
__device__ __half g_Y  [(size_t)2 * HEAD * NE * 512];  // q,k: [p][h][n][lr]
__device__ __half g_Yd [(size_t)HEAD * 512 * NE];      // d:   [h][lr][m]
__device__ __half g_xt [(size_t)NCOL * FEAT];          // xt[(n*8+r)][f]
__device__ __half g_W  [(size_t)3 * HL * FEAT];
__device__ __half g_S  [(size_t)HEAD * NE * NE];       // exp(scores)*rd
__device__ float  g_ss [3 * NE];
__device__ float  g_rs [(size_t)HEAD * NE];

// ---------------- helpers ----------------------------------------------------
__device__ __forceinline__ uint32_t smem_u32(const void* p) {
    uint32_t a;
    asm("{ .reg .u64 t; cvta.to.shared.u64 t, %1; cvt.u32.u64 %0, t; }" : "=r"(a) : "l"(p));
    return a;
}
__device__ __forceinline__ void mma16(float* c, const uint32_t* a, const uint32_t* b) {
    asm volatile(
        "mma.sync.aligned.m16n8k16.row.col.f32.f16.f16.f32 "
        "{%0,%1,%2,%3}, {%4,%5,%6,%7}, {%8,%9}, {%0,%1,%2,%3};"
        : "+f"(c[0]), "+f"(c[1]), "+f"(c[2]), "+f"(c[3])
        : "r"(a[0]), "r"(a[1]), "r"(a[2]), "r"(a[3]), "r"(b[0]), "r"(b[1]));
}
__device__ __forceinline__ void ldsm4(uint32_t* r, uint32_t addr) {
    asm volatile("ldmatrix.sync.aligned.m8n8.x4.shared.b16 {%0,%1,%2,%3}, [%4];"
                 : "=r"(r[0]), "=r"(r[1]), "=r"(r[2]), "=r"(r[3]) : "r"(addr));
}
__device__ __forceinline__ void cp16(uint32_t dst, const void* src) {
    uint64_t g;
    asm("cvta.to.global.u64 %0, %1;" : "=l"(g) : "l"(src));
    asm volatile("cp.async.cg.shared.global [%0], [%1], 16;" :: "r"(dst), "l"(g));
}

// 128 rows x 32 halves K-major tile (128 threads: 4 chunks each)
__device__ __forceinline__ void ld_k(__half* S, const __half* gp, int ldk, int k0, int tid) {
#pragma unroll
    for (int i = 0; i < 4; i++) {
        int idx = tid + i * 128;
        int row = idx >> 2, ch = idx & 3;
        cp16(smem_u32(S + row * PADH + ch * 8), gp + (size_t)row * ldk + k0 + ch * 8);
    }
}

struct Acc { float a[4][8][4]; };

// ---------------- 4-stage pipelined fp16 NT mainloop (ldmatrix) --------------
__device__ __forceinline__ void gemm_main(Acc& F, const __half* A, const __half* B,
                                          int K, __half* sA, __half* sB) {
    const int tid = threadIdx.x;
    const int lane = tid & 31, wid = tid >> 5;
    const int wm = (wid & 1) * 64, wn = (wid >> 1) * 64;

    // ldmatrix per-lane base offsets (in halves):
    // A x4: mid=l>>3 -> row += (mid&1)*8, col += (mid>>1)*8
    const int offA = (wm + (lane & 7) + ((lane >> 3) & 1) * 8) * PADH + ((lane >> 4) & 1) * 8;
    // B x4: mid -> row += (mid>>1)*8 (nt pair), col += (mid&1)*8
    const int offB = (wn + (lane & 7) + ((lane >> 4) & 1) * 8) * PADH + ((lane >> 3) & 1) * 8;

    const uint32_t sA0 = smem_u32(sA), sB0 = smem_u32(sB);

#pragma unroll
    for (int mt = 0; mt < 4; mt++)
#pragma unroll
        for (int nt = 0; nt < 8; nt++)
#pragma unroll
            for (int j = 0; j < 4; j++) F.a[mt][nt][j] = 0.f;

#pragma unroll
    for (int s = 0; s < STG - 1; s++) {
        ld_k(sA + s * ASTRH, A, K, s * BKH, tid);
        ld_k(sB + s * ASTRH, B, K, s * BKH, tid);
        asm volatile("cp.async.commit_group;" ::: "memory");
    }

    const int KT = K / BKH;
    int ls = STG - 1;
    for (int kt = 0; kt < KT; kt++) {
        asm volatile("cp.async.wait_group %0;" :: "n"(STG - 2) : "memory");
        __syncthreads();
        if (kt + STG - 1 < KT) {
            ld_k(sA + ls * ASTRH, A, K, (kt + STG - 1) * BKH, tid);
            ld_k(sB + ls * ASTRH, B, K, (kt + STG - 1) * BKH, tid);
            ls = (ls + 1 == STG) ? 0 : ls + 1;
        }
        asm volatile("cp.async.commit_group;" ::: "memory");

        int buf = kt % STG;
        uint32_t aB = sA0 + (buf * ASTRH + offA) * 2;
        uint32_t bB = sB0 + (buf * ASTRH + offB) * 2;
#pragma unroll
        for (int ks = 0; ks < 2; ks++) {
            uint32_t af[4][4], bf[4][4];
#pragma unroll
            for (int mt = 0; mt < 4; mt++)
                ldsm4(af[mt], aB + (mt * 16 * PADH + 16 * ks) * 2);
#pragma unroll
            for (int np = 0; np < 4; np++)
                ldsm4(bf[np], bB + (np * 16 * PADH + 16 * ks) * 2);
#pragma unroll
            for (int mt = 0; mt < 4; mt++)
#pragma unroll
                for (int np = 0; np < 4; np++) {
                    mma16(F.a[mt][2 * np + 0], af[mt], &bf[np][0]);
                    mma16(F.a[mt][2 * np + 1], af[mt], &bf[np][2]);
                }
        }
    }
    __syncthreads();
}

// ---------------- init / prep / transpose ------------------------------------
__global__ __launch_bounds__(256) void init_zero() {
    int i = blockIdx.x * 256 + threadIdx.x;
    if (i < 3 * NE) g_ss[i] = 0.f;
    if (i < HEAD * NE) g_rs[i] = 0.f;
}
__global__ __launch_bounds__(256) void prep_w(const float* __restrict__ Wq,
                                              const float* __restrict__ Wk,
                                              const float* __restrict__ Wd) {
    int idx = (blockIdx.x * 256 + threadIdx.x) * 4;
    int p = idx >> 18, off = idx & 262143;
    const float* W = (p == 0) ? Wq : (p == 1) ? Wk : Wd;
    float4 t = *(const float4*)(W + off);
    *(__half2*)(g_W + idx)     = make_half2(__float2half_rn(t.x), __float2half_rn(t.y));
    *(__half2*)(g_W + idx + 2) = make_half2(__float2half_rn(t.z), __float2half_rn(t.w));
}
__global__ __launch_bounds__(256) void transpose_x(const float* __restrict__ x) {
    __shared__ float s[512 * 9];
    const int n = blockIdx.x, tid = threadIdx.x;
    const float* src = x + (size_t)n * 4096;
#pragma unroll
    for (int i = 0; i < 4; i++) {
        int v = (tid + i * 256) * 4;
        float4 t = *(const float4*)(src + v);
        int f = v >> 3, rr = v & 7;
        s[f * 9 + rr + 0] = t.x; s[f * 9 + rr + 1] = t.y;
        s[f * 9 + rr + 2] = t.z; s[f * 9 + rr + 3] = t.w;
    }
    __syncthreads();
#pragma unroll
    for (int rr = 0; rr < 8; rr++) {
        int f = tid * 2;
        __half2 h = make_half2(__float2half_rn(s[f * 9 + rr]),
                               __float2half_rn(s[(f + 1) * 9 + rr]));
        *(__half2*)(g_xt + ((size_t)n * 8 + rr) * 512 + f) = h;
    }
}

// ---------------- projection GEMM + fused sum-of-squares --------------------
__global__ __launch_bounds__(128) void proj_tc() {
    extern __shared__ __half dsm[];
    __shared__ float csum[128];
    __half* sA = dsm;
    __half* sB = dsm + STG * ASTRH;
    const int p = blockIdx.z;
    const int m0 = blockIdx.y * 128, c0 = blockIdx.x * 128;

    const int tid = threadIdx.x, lane = tid & 31, wid = tid >> 5;
    const int g8 = lane >> 2, tg = lane & 3;
    const int wm = (wid & 1) * 64, wn = (wid >> 1) * 64;

    if (tid < 128) csum[tid] = 0.f;

    Acc F;
    gemm_main(F, g_W + (size_t)p * HL * FEAT + (size_t)m0 * FEAT,
              g_xt + (size_t)c0 * FEAT, FEAT, sA, sB);

    float sq[8];
#pragma unroll
    for (int nt = 0; nt < 8; nt++) sq[nt] = 0.f;

    if (p < 2) {
        __half* base = g_Y + (size_t)p * HEAD * NE * 512;
#pragma unroll
        for (int mt = 0; mt < 4; mt++)
#pragma unroll
            for (int half = 0; half < 2; half++) {
                int row = m0 + wm + mt * 16 + g8 + half * 8;
                int hh = row >> 6, l = row & 63;
#pragma unroll
                for (int nt = 0; nt < 8; nt++) {
                    int col = c0 + wn + nt * 8 + 2 * tg;
                    int n = col >> 3, r = col & 7;
                    __half h0 = __float2half_rn(F.a[mt][nt][half * 2 + 0]);
                    __half h1 = __float2half_rn(F.a[mt][nt][half * 2 + 1]);
                    float v0 = __half2float(h0), v1 = __half2float(h1);
                    *(__half2*)(base + ((size_t)hh * NE + n) * 512 + l * 8 + r) = make_half2(h0, h1);
                    sq[nt] += v0 * v0 + v1 * v1;
                }
            }
    } else {
        int mb = (c0 >> 3) + (wn >> 3);
#pragma unroll
        for (int mt = 0; mt < 4; mt++)
#pragma unroll
            for (int half = 0; half < 2; half++) {
                int row = m0 + wm + mt * 16 + g8 + half * 8;
                int hh = row >> 6, l = row & 63;
#pragma unroll
                for (int par = 0; par < 2; par++) {
                    __half hv[8];
#pragma unroll
                    for (int nt = 0; nt < 8; nt++) {
                        hv[nt] = __float2half_rn(F.a[mt][nt][half * 2 + par]);
                        float v = __half2float(hv[nt]);
                        sq[nt] += v * v;
                    }
                    int lr = l * 8 + 2 * tg + par;
                    *(uint4*)(g_Yd + ((size_t)hh * 512 + lr) * NE + mb) = *(uint4*)hv;
                }
            }
    }
#pragma unroll
    for (int nt = 0; nt < 8; nt++) {
        float v = sq[nt];
        v += __shfl_down_sync(0xffffffffu, v, 4);
        v += __shfl_down_sync(0xffffffffu, v, 8);
        v += __shfl_down_sync(0xffffffffu, v, 16);
        if (g8 == 0) atomicAdd(&csum[wn + nt * 8 + 2 * tg], v);
    }
    __syncthreads();
    if (tid < 16) {
        float s = 0.f;
#pragma unroll
        for (int j = 0; j < 8; j += 2) s += csum[tid * 8 + j];
        atomicAdd(&g_ss[p * NE + (c0 >> 3) + tid], s);
    }
}

// ---------------- scores GEMM + fused exp/softmax-numerator -----------------
__global__ __launch_bounds__(128) void scores_tc() {
    extern __shared__ __half dsm[];
    __shared__ float rsum[128];
    __half* sA = dsm;
    __half* sB = dsm + STG * ASTRH;
    const int h = blockIdx.z;
    const int m0 = blockIdx.y * 128, n0 = blockIdx.x * 128;

    const int tid = threadIdx.x, lane = tid & 31, wid = tid >> 5;
    const int g8 = lane >> 2, tg = lane & 3;
    const int wm = (wid & 1) * 64, wn = (wid >> 1) * 64;

    if (tid < 128) rsum[tid] = 0.f;

    Acc F;
    gemm_main(F, g_Y + ((size_t)h * NE + m0) * 512,
              g_Y + (((size_t)HEAD + h) * NE + n0) * 512, 512, sA, sB);

    float rk[8][2], rd[8][2];
#pragma unroll
    for (int nt = 0; nt < 8; nt++) {
        int col = n0 + wn + nt * 8 + 2 * tg;
        rk[nt][0] = rsqrtf(g_ss[NE + col]);     rk[nt][1] = rsqrtf(g_ss[NE + col + 1]);
        rd[nt][0] = rsqrtf(g_ss[2 * NE + col]); rd[nt][1] = rsqrtf(g_ss[2 * NE + col + 1]);
    }

#pragma unroll
    for (int mt = 0; mt < 4; mt++)
#pragma unroll
        for (int half = 0; half < 2; half++) {
            int row = m0 + wm + mt * 16 + g8 + half * 8;
            float rq = rsqrtf(g_ss[row]);
            float rs = 0.f;
#pragma unroll
            for (int nt = 0; nt < 8; nt++) {
                int col = n0 + wn + nt * 8 + 2 * tg;
                float e0 = __expf(F.a[mt][nt][half * 2 + 0] * rq * rk[nt][0]);
                float e1 = __expf(F.a[mt][nt][half * 2 + 1] * rq * rk[nt][1]);
                rs += e0 + e1;
                __half2 ph = make_half2(__float2half_rn(e0 * rd[nt][0]),
                                        __float2half_rn(e1 * rd[nt][1]));
                *(__half2*)(g_S + ((size_t)h * NE + row) * NE + col) = ph;
            }
            rs += __shfl_down_sync(0xffffffffu, rs, 1);
            rs += __shfl_down_sync(0xffffffffu, rs, 2);
            if (tg == 0) atomicAdd(&rsum[wm + mt * 16 + g8 + half * 8], rs);
        }
    __syncthreads();
    if (tid < 128) atomicAdd(&g_rs[(size_t)h * NE + m0 + tid], rsum[tid]);
}

// ---------------- combine GEMM (all K-major), scale rows by 1/rowsum --------
__global__ __launch_bounds__(128) void combine_tc(float* __restrict__ out) {
    extern __shared__ __half dsm[];
    __half* sA = dsm;
    __half* sB = dsm + STG * ASTRH;
    const int h = blockIdx.z;
    const int m0 = blockIdx.y * 128, lr0 = blockIdx.x * 128;

    Acc F;
    gemm_main(F, g_S + ((size_t)h * NE + m0) * NE,
              g_Yd + ((size_t)h * 512 + lr0) * NE, NE, sA, sB);

    const int tid = threadIdx.x, lane = tid & 31, wid = tid >> 5;
    const int g8 = lane >> 2, tg = lane & 3;
    const int wm = (wid & 1) * 64, wn = (wid >> 1) * 64;

#pragma unroll
    for (int mt = 0; mt < 4; mt++)
#pragma unroll
        for (int half = 0; half < 2; half++) {
            int row = m0 + wm + mt * 16 + g8 + half * 8;
            float inv = 1.0f / g_rs[(size_t)h * NE + row];
#pragma unroll
            for (int nt = 0; nt < 8; nt++) {
                int col = lr0 + wn + nt * 8 + 2 * tg;
                float v0 = F.a[mt][nt][half * 2 + 0] * inv;
                float v1 = F.a[mt][nt][half * 2 + 1] * inv;
                *(float2*)(out + (size_t)row * OUTC + h * 512 + col) = make_float2(v0, v1);
            }
        }
}

// ---------------------------------------------------------------------------
extern "C" void kernel_launch(void* const* d_in, const int* in_sizes, int n_in,
                              void* d_out, int out_size) {
    const float* x  = (const float*)d_in[0];
    const float* Wq = (const float*)d_in[1];
    const float* Wk = (const float*)d_in[2];
    const float* Wd = (const float*)d_in[3];
    float* out = (float*)d_out;

    cudaFuncSetAttribute(proj_tc,    cudaFuncAttributeMaxDynamicSharedMemorySize, SMEM_BYTES);
    cudaFuncSetAttribute(scores_tc,  cudaFuncAttributeMaxDynamicSharedMemorySize, SMEM_BYTES);
    cudaFuncSetAttribute(combine_tc, cudaFuncAttributeMaxDynamicSharedMemorySize, SMEM_BYTES);

    init_zero<<<64, 256>>>();
    prep_w<<<768, 256>>>(Wq, Wk, Wd);
    transpose_x<<<NE, 256>>>(x);
    proj_tc<<<dim3(NCOL / 128, HL / 128, 3), 128, SMEM_BYTES>>>();
    scores_tc<<<dim3(NE / 128, NE / 128, HEAD), 128, SMEM_BYTES>>>();
    combine_tc<<<dim3(512 / 128, NE / 128, HEAD), 128, SMEM_BYTES>>>(out);
}

// round 10
// speedup vs baseline: 2.0413x; 1.0407x over previous
#include <cuda_runtime.h>
#include <cuda_fp16.h>
#include <math.h>
#include <stdint.h>

#define NE    2048
#define FEAT  512
#define REST  8
#define HEAD  8
#define HL    512
#define NCOL  16384
#define OUTC  (HEAD*512)
#define BKH   64                  // K per smem stage, in halves
#define PADH  72                  // halves per row (144B stride -> ldmatrix conflict-free)
#define ASTRH (128*PADH)
#define STG   3
#define SMEM_BYTES (2 * STG * ASTRH * 2)   // 110592 bytes

// ---------------- scratch ----------------------------------------------------
__device__ __half g_Y  [(size_t)2 * HEAD * NE * 512];  // q,k: [p][h][n][lr]
__device__ __half g_Yd [(size_t)HEAD * 512 * NE];      // d:   [h][lr][m]
__device__ __half g_xt [(size_t)NCOL * FEAT];          // xt[(n*8+r)][f]
__device__ __half g_W  [(size_t)3 * HL * FEAT];
__device__ __half g_S  [(size_t)HEAD * NE * NE];       // exp(scores)*rd
__device__ float  g_ss [3 * NE];
__device__ float  g_rs [(size_t)HEAD * NE];

// ---------------- helpers ----------------------------------------------------
__device__ __forceinline__ uint32_t smem_u32(const void* p) {
    uint32_t a;
    asm("{ .reg .u64 t; cvta.to.shared.u64 t, %1; cvt.u32.u64 %0, t; }" : "=r"(a) : "l"(p));
    return a;
}
__device__ __forceinline__ void mma16(float* c, const uint32_t* a, const uint32_t* b) {
    asm volatile(
        "mma.sync.aligned.m16n8k16.row.col.f32.f16.f16.f32 "
        "{%0,%1,%2,%3}, {%4,%5,%6,%7}, {%8,%9}, {%0,%1,%2,%3};"
        : "+f"(c[0]), "+f"(c[1]), "+f"(c[2]), "+f"(c[3])
        : "r"(a[0]), "r"(a[1]), "r"(a[2]), "r"(a[3]), "r"(b[0]), "r"(b[1]));
}
__device__ __forceinline__ void ldsm4(uint32_t* r, uint32_t addr) {
    asm volatile("ldmatrix.sync.aligned.m8n8.x4.shared.b16 {%0,%1,%2,%3}, [%4];"
                 : "=r"(r[0]), "=r"(r[1]), "=r"(r[2]), "=r"(r[3]) : "r"(addr));
}
__device__ __forceinline__ void cp16(uint32_t dst, const void* src) {
    uint64_t g;
    asm("cvta.to.global.u64 %0, %1;" : "=l"(g) : "l"(src));
    asm volatile("cp.async.cg.shared.global [%0], [%1], 16;" :: "r"(dst), "l"(g));
}

// 128 rows x 64 halves K-major tile (128 threads: 8 chunks each)
__device__ __forceinline__ void ld_k(__half* S, const __half* gp, int ldk, int k0, int tid) {
#pragma unroll
    for (int i = 0; i < 8; i++) {
        int idx = tid + i * 128;
        int row = idx >> 3, ch = idx & 7;
        cp16(smem_u32(S + row * PADH + ch * 8), gp + (size_t)row * ldk + k0 + ch * 8);
    }
}

struct Acc { float a[4][8][4]; };

// ---------------- 3-stage, BK=64, fragment double-buffered mainloop ----------
__device__ __forceinline__ void gemm_main(Acc& F, const __half* A, const __half* B,
                                          int K, __half* sA, __half* sB) {
    const int tid = threadIdx.x;
    const int lane = tid & 31, wid = tid >> 5;
    const int wm = (wid & 1) * 64, wn = (wid >> 1) * 64;

    const int offA = (wm + (lane & 7) + ((lane >> 3) & 1) * 8) * PADH + ((lane >> 4) & 1) * 8;
    const int offB = (wn + (lane & 7) + ((lane >> 4) & 1) * 8) * PADH + ((lane >> 3) & 1) * 8;

    const uint32_t sA0 = smem_u32(sA), sB0 = smem_u32(sB);

#pragma unroll
    for (int mt = 0; mt < 4; mt++)
#pragma unroll
        for (int nt = 0; nt < 8; nt++)
#pragma unroll
            for (int j = 0; j < 4; j++) F.a[mt][nt][j] = 0.f;

#pragma unroll
    for (int s = 0; s < STG - 1; s++) {
        ld_k(sA + s * ASTRH, A, K, s * BKH, tid);
        ld_k(sB + s * ASTRH, B, K, s * BKH, tid);
        asm volatile("cp.async.commit_group;" ::: "memory");
    }

    const int KT = K / BKH;
    int ls = STG - 1;
    for (int kt = 0; kt < KT; kt++) {
        asm volatile("cp.async.wait_group %0;" :: "n"(STG - 2) : "memory");
        __syncthreads();
        if (kt + STG - 1 < KT) {
            ld_k(sA + ls * ASTRH, A, K, (kt + STG - 1) * BKH, tid);
            ld_k(sB + ls * ASTRH, B, K, (kt + STG - 1) * BKH, tid);
            ls = (ls + 1 == STG) ? 0 : ls + 1;
        }
        asm volatile("cp.async.commit_group;" ::: "memory");

        int buf = kt % STG;
        const uint32_t aB = sA0 + (buf * ASTRH + offA) * 2;
        const uint32_t bB = sB0 + (buf * ASTRH + offB) * 2;

        uint32_t af[2][4][4], bf[2][4][4];
#pragma unroll
        for (int mt = 0; mt < 4; mt++) ldsm4(af[0][mt], aB + (mt * 16 * PADH) * 2);
#pragma unroll
        for (int np = 0; np < 4; np++) ldsm4(bf[0][np], bB + (np * 16 * PADH) * 2);

#pragma unroll
        for (int ks = 0; ks < 4; ks++) {           // 4 x k16 per 64-K stage
            int cur = ks & 1, nxt = cur ^ 1;
            if (ks < 3) {
#pragma unroll
                for (int mt = 0; mt < 4; mt++)
                    ldsm4(af[nxt][mt], aB + (mt * 16 * PADH + 16 * (ks + 1)) * 2);
#pragma unroll
                for (int np = 0; np < 4; np++)
                    ldsm4(bf[nxt][np], bB + (np * 16 * PADH + 16 * (ks + 1)) * 2);
            }
#pragma unroll
            for (int mt = 0; mt < 4; mt++)
#pragma unroll
                for (int np = 0; np < 4; np++) {
                    mma16(F.a[mt][2 * np + 0], af[cur][mt], &bf[cur][np][0]);
                    mma16(F.a[mt][2 * np + 1], af[cur][mt], &bf[cur][np][2]);
                }
        }
    }
    __syncthreads();
}

// ---------------- init / prep / transpose ------------------------------------
__global__ __launch_bounds__(256) void init_zero() {
    int i = blockIdx.x * 256 + threadIdx.x;
    if (i < 3 * NE) g_ss[i] = 0.f;
    if (i < HEAD * NE) g_rs[i] = 0.f;
}
__global__ __launch_bounds__(256) void prep_w(const float* __restrict__ Wq,
                                              const float* __restrict__ Wk,
                                              const float* __restrict__ Wd) {
    int idx = (blockIdx.x * 256 + threadIdx.x) * 4;
    int p = idx >> 18, off = idx & 262143;
    const float* W = (p == 0) ? Wq : (p == 1) ? Wk : Wd;
    float4 t = *(const float4*)(W + off);
    *(__half2*)(g_W + idx)     = make_half2(__float2half_rn(t.x), __float2half_rn(t.y));
    *(__half2*)(g_W + idx + 2) = make_half2(__float2half_rn(t.z), __float2half_rn(t.w));
}
__global__ __launch_bounds__(256) void transpose_x(const float* __restrict__ x) {
    __shared__ float s[512 * 9];
    const int n = blockIdx.x, tid = threadIdx.x;
    const float* src = x + (size_t)n * 4096;
#pragma unroll
    for (int i = 0; i < 4; i++) {
        int v = (tid + i * 256) * 4;
        float4 t = *(const float4*)(src + v);
        int f = v >> 3, rr = v & 7;
        s[f * 9 + rr + 0] = t.x; s[f * 9 + rr + 1] = t.y;
        s[f * 9 + rr + 2] = t.z; s[f * 9 + rr + 3] = t.w;
    }
    __syncthreads();
#pragma unroll
    for (int rr = 0; rr < 8; rr++) {
        int f = tid * 2;
        __half2 h = make_half2(__float2half_rn(s[f * 9 + rr]),
                               __float2half_rn(s[(f + 1) * 9 + rr]));
        *(__half2*)(g_xt + ((size_t)n * 8 + rr) * 512 + f) = h;
    }
}

// ---------------- projection GEMM + fused sum-of-squares --------------------
__global__ __launch_bounds__(128) void proj_tc() {
    extern __shared__ __half dsm[];
    __shared__ float csum[128];
    __half* sA = dsm;
    __half* sB = dsm + STG * ASTRH;
    const int p = blockIdx.z;
    const int m0 = blockIdx.y * 128, c0 = blockIdx.x * 128;

    const int tid = threadIdx.x, lane = tid & 31, wid = tid >> 5;
    const int g8 = lane >> 2, tg = lane & 3;
    const int wm = (wid & 1) * 64, wn = (wid >> 1) * 64;

    if (tid < 128) csum[tid] = 0.f;

    Acc F;
    gemm_main(F, g_W + (size_t)p * HL * FEAT + (size_t)m0 * FEAT,
              g_xt + (size_t)c0 * FEAT, FEAT, sA, sB);

    float sq[8];
#pragma unroll
    for (int nt = 0; nt < 8; nt++) sq[nt] = 0.f;

    if (p < 2) {
        __half* base = g_Y + (size_t)p * HEAD * NE * 512;
#pragma unroll
        for (int mt = 0; mt < 4; mt++)
#pragma unroll
            for (int half = 0; half < 2; half++) {
                int row = m0 + wm + mt * 16 + g8 + half * 8;
                int hh = row >> 6, l = row & 63;
#pragma unroll
                for (int nt = 0; nt < 8; nt++) {
                    int col = c0 + wn + nt * 8 + 2 * tg;
                    int n = col >> 3, r = col & 7;
                    __half h0 = __float2half_rn(F.a[mt][nt][half * 2 + 0]);
                    __half h1 = __float2half_rn(F.a[mt][nt][half * 2 + 1]);
                    float v0 = __half2float(h0), v1 = __half2float(h1);
                    *(__half2*)(base + ((size_t)hh * NE + n) * 512 + l * 8 + r) = make_half2(h0, h1);
                    sq[nt] += v0 * v0 + v1 * v1;
                }
            }
    } else {
        int mb = (c0 >> 3) + (wn >> 3);
#pragma unroll
        for (int mt = 0; mt < 4; mt++)
#pragma unroll
            for (int half = 0; half < 2; half++) {
                int row = m0 + wm + mt * 16 + g8 + half * 8;
                int hh = row >> 6, l = row & 63;
#pragma unroll
                for (int par = 0; par < 2; par++) {
                    __half hv[8];
#pragma unroll
                    for (int nt = 0; nt < 8; nt++) {
                        hv[nt] = __float2half_rn(F.a[mt][nt][half * 2 + par]);
                        float v = __half2float(hv[nt]);
                        sq[nt] += v * v;
                    }
                    int lr = l * 8 + 2 * tg + par;
                    *(uint4*)(g_Yd + ((size_t)hh * 512 + lr) * NE + mb) = *(uint4*)hv;
                }
            }
    }
#pragma unroll
    for (int nt = 0; nt < 8; nt++) {
        float v = sq[nt];
        v += __shfl_down_sync(0xffffffffu, v, 4);
        v += __shfl_down_sync(0xffffffffu, v, 8);
        v += __shfl_down_sync(0xffffffffu, v, 16);
        if (g8 == 0) atomicAdd(&csum[wn + nt * 8 + 2 * tg], v);
    }
    __syncthreads();
    if (tid < 16) {
        float s = 0.f;
#pragma unroll
        for (int j = 0; j < 8; j += 2) s += csum[tid * 8 + j];
        atomicAdd(&g_ss[p * NE + (c0 >> 3) + tid], s);
    }
}

// ---------------- scores GEMM + fused exp/softmax-numerator -----------------
__global__ __launch_bounds__(128) void scores_tc() {
    extern __shared__ __half dsm[];
    __shared__ float rsum[128];
    __half* sA = dsm;
    __half* sB = dsm + STG * ASTRH;
    const int h = blockIdx.z;
    const int m0 = blockIdx.y * 128, n0 = blockIdx.x * 128;

    const int tid = threadIdx.x, lane = tid & 31, wid = tid >> 5;
    const int g8 = lane >> 2, tg = lane & 3;
    const int wm = (wid & 1) * 64, wn = (wid >> 1) * 64;

    if (tid < 128) rsum[tid] = 0.f;

    Acc F;
    gemm_main(F, g_Y + ((size_t)h * NE + m0) * 512,
              g_Y + (((size_t)HEAD + h) * NE + n0) * 512, 512, sA, sB);

    float rk[8][2], rd[8][2];
#pragma unroll
    for (int nt = 0; nt < 8; nt++) {
        int col = n0 + wn + nt * 8 + 2 * tg;
        rk[nt][0] = rsqrtf(g_ss[NE + col]);     rk[nt][1] = rsqrtf(g_ss[NE + col + 1]);
        rd[nt][0] = rsqrtf(g_ss[2 * NE + col]); rd[nt][1] = rsqrtf(g_ss[2 * NE + col + 1]);
    }

#pragma unroll
    for (int mt = 0; mt < 4; mt++)
#pragma unroll
        for (int half = 0; half < 2; half++) {
            int row = m0 + wm + mt * 16 + g8 + half * 8;
            float rq = rsqrtf(g_ss[row]);
            float rs = 0.f;
#pragma unroll
            for (int nt = 0; nt < 8; nt++) {
                int col = n0 + wn + nt * 8 + 2 * tg;
                float e0 = __expf(F.a[mt][nt][half * 2 + 0] * rq * rk[nt][0]);
                float e1 = __expf(F.a[mt][nt][half * 2 + 1] * rq * rk[nt][1]);
                rs += e0 + e1;
                __half2 ph = make_half2(__float2half_rn(e0 * rd[nt][0]),
                                        __float2half_rn(e1 * rd[nt][1]));
                *(__half2*)(g_S + ((size_t)h * NE + row) * NE + col) = ph;
            }
            rs += __shfl_down_sync(0xffffffffu, rs, 1);
            rs += __shfl_down_sync(0xffffffffu, rs, 2);
            if (tg == 0) atomicAdd(&rsum[wm + mt * 16 + g8 + half * 8], rs);
        }
    __syncthreads();
    if (tid < 128) atomicAdd(&g_rs[(size_t)h * NE + m0 + tid], rsum[tid]);
}

// ---------------- combine GEMM (all K-major), scale rows by 1/rowsum --------
__global__ __launch_bounds__(128) void combine_tc(float* __restrict__ out) {
    extern __shared__ __half dsm[];
    __half* sA = dsm;
    __half* sB = dsm + STG * ASTRH;
    const int h = blockIdx.z;
    const int m0 = blockIdx.y * 128, lr0 = blockIdx.x * 128;

    Acc F;
    gemm_main(F, g_S + ((size_t)h * NE + m0) * NE,
              g_Yd + ((size_t)h * 512 + lr0) * NE, NE, sA, sB);

    const int tid = threadIdx.x, lane = tid & 31, wid = tid >> 5;
    const int g8 = lane >> 2, tg = lane & 3;
    const int wm = (wid & 1) * 64, wn = (wid >> 1) * 64;

#pragma unroll
    for (int mt = 0; mt < 4; mt++)
#pragma unroll
        for (int half = 0; half < 2; half++) {
            int row = m0 + wm + mt * 16 + g8 + half * 8;
            float inv = 1.0f / g_rs[(size_t)h * NE + row];
#pragma unroll
            for (int nt = 0; nt < 8; nt++) {
                int col = lr0 + wn + nt * 8 + 2 * tg;
                float v0 = F.a[mt][nt][half * 2 + 0] * inv;
                float v1 = F.a[mt][nt][half * 2 + 1] * inv;
                *(float2*)(out + (size_t)row * OUTC + h * 512 + col) = make_float2(v0, v1);
            }
        }
}

// ---------------------------------------------------------------------------
extern "C" void kernel_launch(void* const* d_in, const int* in_sizes, int n_in,
                              void* d_out, int out_size) {
    const float* x  = (const float*)d_in[0];
    const float* Wq = (const float*)d_in[1];
    const float* Wk = (const float*)d_in[2];
    const float* Wd = (const float*)d_in[3];
    float* out = (float*)d_out;

    cudaFuncSetAttribute(proj_tc,    cudaFuncAttributeMaxDynamicSharedMemorySize, SMEM_BYTES);
    cudaFuncSetAttribute(scores_tc,  cudaFuncAttributeMaxDynamicSharedMemorySize, SMEM_BYTES);
    cudaFuncSetAttribute(combine_tc, cudaFuncAttributeMaxDynamicSharedMemorySize, SMEM_BYTES);

    init_zero<<<64, 256>>>();
    prep_w<<<768, 256>>>(Wq, Wk, Wd);
    transpose_x<<<NE, 256>>>(x);
    proj_tc<<<dim3(NCOL / 128, HL / 128, 3), 128, SMEM_BYTES>>>();
    scores_tc<<<dim3(NE / 128, NE / 128, HEAD), 128, SMEM_BYTES>>>();
    combine_tc<<<dim3(512 / 128, NE / 128, HEAD), 128, SMEM_BYTES>>>(out);
}